// round 4
// baseline (speedup 1.0000x reference)
#include <cuda_runtime.h>
#include <cstddef>

namespace {
constexpr int Bn  = 1024;
constexpr int Tn  = 512;
constexpr int Hn  = 64;
constexpr int NB  = 8;      // batch rows per recurrence block -> grid 128
}

// Inter-layer hidden sequences, [t][b][64] token-major.
__device__ float g_seq0[(size_t)Tn * Bn * Hn];
__device__ float g_seq1[(size_t)Tn * Bn * Hn];
// Layer-0 input transposed+padded: [t][b][32] (cols 22..31 zero)
__device__ float g_xT[(size_t)Tn * Bn * 32];
// Per-layer x-projection gates (reused across layers): [t][b][256]
__device__ float g_gx[(size_t)Tn * Bn * 256];

using u64 = unsigned long long;

__device__ __forceinline__ u64 fma2(u64 a, u64 b, u64 c) {
    u64 d;
    asm("fma.rn.f32x2 %0, %1, %2, %3;" : "=l"(d) : "l"(a), "l"(b), "l"(c));
    return d;
}
__device__ __forceinline__ u64 pack2(float lo, float hi) {
    return ((u64)__float_as_uint(hi) << 32) | (u64)__float_as_uint(lo);
}
__device__ __forceinline__ float hadd2(u64 a) {
    return __uint_as_float((unsigned)a) + __uint_as_float((unsigned)(a >> 32));
}
__device__ __forceinline__ float sigm(float x) {
    return __fdividef(1.f, 1.f + __expf(-x));
}
__device__ __forceinline__ float tanh_(float x) {
    return __fdividef(2.f, 1.f + __expf(-2.f * x)) - 1.f;
}

// Transpose x[b][22][t] -> g_xT[t][b][0..31] (pad 22..31 with 0).
__global__ void __launch_bounds__(256)
transpose_x_k(const float* __restrict__ x)
{
    const int b  = blockIdx.x >> 3;
    const int t0 = (blockIdx.x & 7) * 64;
    __shared__ float tile[22][65];
    for (int e = threadIdx.x; e < 22 * 64; e += 256) {
        int i = e / 64, tt = e - i * 64;
        tile[i][tt] = x[(size_t)b * (22 * Tn) + i * Tn + t0 + tt];
    }
    __syncthreads();
    for (int e = threadIdx.x; e < 64 * 32; e += 256) {
        int tt = e >> 5, i = e & 31;
        g_xT[((size_t)(t0 + tt) * Bn + b) * 32 + i] = (i < 22) ? tile[i][tt] : 0.f;
    }
}

// Batch x-projection: gx[token][g] = in[token][:] . w_ih[g][:] + b_ih[g] + b_hh[g]
// for all T*B tokens. Block = 1024 threads, thread = (g = tid&255, kq = tid>>8),
// weights register-resident; 8 tokens per iteration; 4-way K reduction via smem.
template<int DINP>    // 32 (layer 0, DIN=22 padded) or 64
__global__ void __launch_bounds__(1024, 1)
xproj_k(const float* __restrict__ in, const float* __restrict__ w_ih,
        const float* __restrict__ b_ih, const float* __restrict__ b_hh)
{
    constexpr int DIN   = (DINP == 32) ? 22 : 64;
    constexpr int PAIRS = DINP / 2;     // 16 or 32
    constexpr int PP    = PAIRS / 4;    // pairs per K-quarter: 4 or 8
    constexpr int ITERS = 512;          // 8 tokens each -> 4096 tokens per block

    const int tid = threadIdx.x;
    const int g   = tid & 255;
    const int kq  = tid >> 8;           // K-quarter 0..3
    const size_t tok0 = (size_t)blockIdx.x * 4096;

    __shared__ __align__(16) float x_s[8][DINP];
    __shared__ float part[4][8][256];

    u64 w[PP];
#pragma unroll
    for (int pp = 0; pp < PP; pp++) {
        const int c0 = 2 * (kq * PP + pp);
        float lo = (c0     < DIN) ? w_ih[g * DIN + c0]     : 0.f;
        float hi = (c0 + 1 < DIN) ? w_ih[g * DIN + c0 + 1] : 0.f;
        w[pp] = pack2(lo, hi);
    }
    const float bias = b_ih[g] + b_hh[g];

    const bool act = tid < 8 * DINP;
    const int  sr  = tid / DINP;
    const int  si  = tid % DINP;
    float xreg = 0.f;
    if (act) xreg = in[(tok0 + sr) * DINP + si];

    const int tp = tid >> 8;            // output token-pair slot 0..3

    for (int it = 0; it < ITERS; it++) {
        if (act) x_s[sr][si] = xreg;
        __syncthreads();    // S1: tokens staged; prev part reads done

        u64 a[8];
#pragma unroll
        for (int r = 0; r < 8; r++) a[r] = 0ull;
#pragma unroll
        for (int q = 0; q < PP / 2; q++) {
#pragma unroll
            for (int r = 0; r < 8; r++) {
                ulonglong2 v = reinterpret_cast<const ulonglong2*>(&x_s[r][0])[kq * (PP / 2) + q];
                a[r] = fma2(w[2 * q],     v.x, a[r]);
                a[r] = fma2(w[2 * q + 1], v.y, a[r]);
            }
        }
        if (act && it + 1 < ITERS)
            xreg = in[(tok0 + (size_t)(it + 1) * 8 + sr) * DINP + si];
#pragma unroll
        for (int r = 0; r < 8; r++)
            part[kq][r][g] = hadd2(a[r]);
        __syncthreads();    // S2: partials ready

#pragma unroll
        for (int u = 0; u < 2; u++) {
            const int r = tp * 2 + u;
            float s = part[0][r][g] + part[1][r][g] + part[2][r][g] + part[3][r][g] + bias;
            g_gx[(tok0 + (size_t)it * 8 + r) * 256 + g] = s;
        }
    }
}

// Recurrence only: gates = gx(t) + h(t-1) @ w_hh^T. Block owns 8 batch rows.
// 1024 threads: thread = (g = tid&255, ks = (tid>>8)&1 K-half, rh = tid>>9 row-half).
// Each thread: gate g, 4 rows, 32 of 64 K. 2-way K reduction via smem.
// Combine thread (tid<512): cell (r = tid>>6, c = tid&63), cell state in reg.
template<bool LAST>
__global__ void __launch_bounds__(1024, 1)
lstm_rec_k(const float* __restrict__ w_hh,
           float* __restrict__ outs,
           const float* __restrict__ w_fc, const float* __restrict__ b_fc,
           float* __restrict__ out_fc)
{
    const int tid = threadIdx.x;
    const int g   = tid & 255;
    const int sub = tid >> 8;
    const int ks  = sub & 1;
    const int rh  = sub >> 1;
    const int b0  = blockIdx.x * NB;

    __shared__ __align__(16) float h_s[NB][Hn];
    __shared__ float part[2][NB][256];

    // register weights: w_hh[g][ks*32 .. ks*32+31] as 16 f32x2 pairs
    u64 w[16];
#pragma unroll
    for (int p = 0; p < 16; p++) {
        const int c0 = ks * 32 + 2 * p;
        w[p] = pack2(w_hh[g * Hn + c0], w_hh[g * Hn + c0 + 1]);
    }

    for (int e = tid; e < NB * Hn; e += 1024)
        (&h_s[0][0])[e] = 0.f;

    const int cr = tid >> 6;
    const int cc = tid & 63;
    float cst = 0.f;

    float xpr[4];
    if (ks == 0) {
#pragma unroll
        for (int j = 0; j < 4; j++)
            xpr[j] = g_gx[((size_t)0 * Bn + b0 + rh * 4 + j) * 256 + g];
    }

    for (int t = 0; t < Tn; t++) {
        __syncthreads();    // S1: h(t-1) visible; prev part reads done

        u64 a[4];
#pragma unroll
        for (int j = 0; j < 4; j++)
            a[j] = (ks == 0) ? pack2(xpr[j], 0.f) : 0ull;
#pragma unroll
        for (int q = 0; q < 8; q++) {
#pragma unroll
            for (int j = 0; j < 4; j++) {
                ulonglong2 v = reinterpret_cast<const ulonglong2*>(&h_s[rh * 4 + j][0])[ks * 8 + q];
                a[j] = fma2(w[2 * q],     v.x, a[j]);
                a[j] = fma2(w[2 * q + 1], v.y, a[j]);
            }
        }

        // prefetch next step's x-projection (hidden behind S2 + combine)
        if (ks == 0 && t + 1 < Tn) {
#pragma unroll
            for (int j = 0; j < 4; j++)
                xpr[j] = g_gx[((size_t)(t + 1) * Bn + b0 + rh * 4 + j) * 256 + g];
        }

#pragma unroll
        for (int j = 0; j < 4; j++)
            part[ks][rh * 4 + j][g] = hadd2(a[j]);
        __syncthreads();    // S2: partials ready

        if (tid < NB * Hn) {
            float gi = part[0][cr][cc]       + part[1][cr][cc];
            float gf = part[0][cr][64  + cc] + part[1][cr][64  + cc];
            float gg = part[0][cr][128 + cc] + part[1][cr][128 + cc];
            float go = part[0][cr][192 + cc] + part[1][cr][192 + cc];
            float iv = sigm(gi), fv = sigm(gf), gv = tanh_(gg), ov = sigm(go);
            cst = fv * cst + iv * gv;
            float h = ov * tanh_(cst);
            h_s[cr][cc] = h;
            if constexpr (!LAST)
                outs[((size_t)t * Bn + b0 + cr) * Hn + cc] = h;
        }
        // next S1 orders combine writes before next phase A
    }

    if constexpr (LAST) {
        __syncthreads();
        if (tid < NB * 4) {
            const int r = tid >> 2, o = tid & 3;
            float s = b_fc[o];
#pragma unroll
            for (int k = 0; k < Hn; k++)
                s += h_s[r][k] * w_fc[o * Hn + k];
            out_fc[(b0 + r) * 4 + o] = s;
        }
    }
}

extern "C" void kernel_launch(void* const* d_in, const int* in_sizes, int n_in,
                              void* d_out, int out_size)
{
    const float* x    = (const float*)d_in[0];
    const float* wih0 = (const float*)d_in[1];
    const float* whh0 = (const float*)d_in[2];
    const float* bih0 = (const float*)d_in[3];
    const float* bhh0 = (const float*)d_in[4];
    const float* wih1 = (const float*)d_in[5];
    const float* whh1 = (const float*)d_in[6];
    const float* bih1 = (const float*)d_in[7];
    const float* bhh1 = (const float*)d_in[8];
    const float* wih2 = (const float*)d_in[9];
    const float* whh2 = (const float*)d_in[10];
    const float* bih2 = (const float*)d_in[11];
    const float* bhh2 = (const float*)d_in[12];
    const float* wfc  = (const float*)d_in[13];
    const float* bfc  = (const float*)d_in[14];
    float* out = (float*)d_out;

    float* seq0 = nullptr, * seq1 = nullptr, * xT = nullptr;
    cudaGetSymbolAddress((void**)&seq0, g_seq0);
    cudaGetSymbolAddress((void**)&seq1, g_seq1);
    cudaGetSymbolAddress((void**)&xT,   g_xT);

    dim3 gridR(Bn / NB);      // 128
    dim3 gridX(128);          // 4096 tokens each

    transpose_x_k<<<Bn * 8, 256>>>(x);

    xproj_k<32><<<gridX, 1024>>>(xT,   wih0, bih0, bhh0);
    lstm_rec_k<false><<<gridR, 1024>>>(whh0, seq0, nullptr, nullptr, nullptr);

    xproj_k<64><<<gridX, 1024>>>(seq0, wih1, bih1, bhh1);
    lstm_rec_k<false><<<gridR, 1024>>>(whh1, seq1, nullptr, nullptr, nullptr);

    xproj_k<64><<<gridX, 1024>>>(seq1, wih2, bih2, bhh2);
    lstm_rec_k<true><<<gridR, 1024>>>(whh2, nullptr, wfc, bfc, out);
}

// round 5
// speedup vs baseline: 1.6508x; 1.6508x over previous
#include <cuda_runtime.h>
#include <cstddef>

namespace {
constexpr int Bn   = 1024;
constexpr int BnP  = 1032;   // padded rows (zero tail) so tail block can read freely
constexpr int Tn   = 512;
constexpr int Hn   = 64;
constexpr int NB   = 7;      // batch rows per block -> grid = 147 (of 148 SMs)
constexpr int GRID = 147;
constexpr int NT   = 512;    // threads per block (16 warps)
}

// Inter-layer hidden sequences, [t][b][h], b padded to 1032 (rows >=1024 stay 0).
__device__ float g_seq0[(size_t)Tn * BnP * Hn];
__device__ float g_seq1[(size_t)Tn * BnP * Hn];
// Layer-0 input transposed+padded: [t][b][32] (cols 22..31 zero, rows >=1024 zero)
__device__ float g_xT[(size_t)Tn * BnP * 32];

using u64 = unsigned long long;

__device__ __forceinline__ u64 fma2(u64 a, u64 b, u64 c) {
    u64 d;
    asm("fma.rn.f32x2 %0, %1, %2, %3;" : "=l"(d) : "l"(a), "l"(b), "l"(c));
    return d;
}
__device__ __forceinline__ u64 pack2(float lo, float hi) {
    return ((u64)__float_as_uint(hi) << 32) | (u64)__float_as_uint(lo);
}
__device__ __forceinline__ float hadd2(u64 a) {
    return __uint_as_float((unsigned)a) + __uint_as_float((unsigned)(a >> 32));
}
__device__ __forceinline__ float sigm(float x) {
    return __fdividef(1.f, 1.f + __expf(-x));
}
__device__ __forceinline__ float tanh_(float x) {
    return __fdividef(2.f, 1.f + __expf(-2.f * x)) - 1.f;
}

// Transpose x[b][22][t] -> g_xT[t][b][0..31] (pad 22..31 with 0).
__global__ void __launch_bounds__(256)
transpose_x_k(const float* __restrict__ x)
{
    const int b  = blockIdx.x >> 3;
    const int t0 = (blockIdx.x & 7) * 64;
    __shared__ float tile[22][65];
    for (int e = threadIdx.x; e < 22 * 64; e += 256) {
        int i = e / 64, tt = e - i * 64;
        tile[i][tt] = x[(size_t)b * (22 * Tn) + i * Tn + t0 + tt];
    }
    __syncthreads();
    for (int e = threadIdx.x; e < 64 * 32; e += 256) {
        int tt = e >> 5, i = e & 31;
        g_xT[((size_t)(t0 + tt) * BnP + b) * 32 + i] = (i < 22) ? tile[i][tt] : 0.f;
    }
}

// One LSTM layer. Block owns up to NB=7 batch rows for all T steps.
// Thread (ks = tid>>7, gp = tid&127) computes gates {2gp, 2gp+1} over
// K-quarter ks for all 7 rows (weights register-resident as f32x2 pairs).
// Partials reduced through smem; combine thread (tid<448: r = tid>>6,
// c = tid&63) owns cell (r,c) and keeps its cell state in a register.
template<int LAYER>
__global__ void __launch_bounds__(NT, 1)
lstm_layer_k(const float* __restrict__ w_ih, const float* __restrict__ w_hh,
             const float* __restrict__ b_ih, const float* __restrict__ b_hh,
             const float* __restrict__ w_fc, const float* __restrict__ b_fc,
             float* __restrict__ out_fc)
{
    constexpr bool FIRST = (LAYER == 0);
    constexpr bool LAST  = (LAYER == 2);
    constexpr int DIN   = FIRST ? 22 : Hn;
    constexpr int DINP  = FIRST ? 32 : Hn;      // padded x width
    constexpr int INLEN = DINP + Hn;            // 96 or 128 floats
    constexpr int NPAIR = INLEN / 2;            // 48 or 64 f32x2 pairs
    constexpr int PP    = NPAIR / 4;            // pairs per K-quarter: 12 or 16

    const float* in;
    if constexpr (LAYER == 0)      in = g_xT;
    else if constexpr (LAYER == 1) in = g_seq0;
    else                           in = g_seq1;
    float* outs;
    if constexpr (LAYER == 0)      outs = g_seq0;
    else if constexpr (LAYER == 1) outs = g_seq1;
    else                           outs = nullptr;

    const int tid = threadIdx.x;
    const int ks  = tid >> 7;          // K-quarter 0..3
    const int gp  = tid & 127;         // gate pair
    const int g0  = 2 * gp;
    const int b0  = blockIdx.x * NB;
    const int nrows = (Bn - b0 < NB) ? (Bn - b0) : NB;   // 7, tail block 2

    __shared__ __align__(16) float in_s[NB][INLEN];   // [x_t | h_{t-1}] per row
    __shared__ float part[NB][4][256];                // K-quarter partial gate sums

    // ---- register-resident weights for 2 gates x PP pairs ----
    u64 w[2][PP];
#pragma unroll
    for (int gg = 0; gg < 2; gg++) {
        const int g = g0 + gg;
#pragma unroll
        for (int pp = 0; pp < PP; pp++) {
            const int p = ks * PP + pp;            // global pair index
            float lo, hi;
            if (p < DINP / 2) {
                const int c0 = 2 * p;
                lo = (c0     < DIN) ? w_ih[g * DIN + c0]     : 0.f;
                hi = (c0 + 1 < DIN) ? w_ih[g * DIN + c0 + 1] : 0.f;
            } else {
                const int c0 = 2 * (p - DINP / 2);
                lo = w_hh[g * Hn + c0];
                hi = w_hh[g * Hn + c0 + 1];
            }
            w[gg][pp] = pack2(lo, hi);
        }
    }
    const u64 binit0 = (ks == 0) ? pack2(b_ih[g0]     + b_hh[g0],     0.f) : 0ull;
    const u64 binit1 = (ks == 0) ? pack2(b_ih[g0 + 1] + b_hh[g0 + 1], 0.f) : 0ull;

    // zero smem input buffer (h starts at 0, x pad stays 0)
    for (int e = tid; e < NB * INLEN; e += NT)
        (&in_s[0][0])[e] = 0.f;

    // staging identity (1 global float per thread per step; padded rows read 0)
    const bool act = FIRST ? (tid < NB * 32) : (tid < NB * Hn);
    const int  sr  = FIRST ? (tid >> 5) : (tid >> 6);
    const int  si  = FIRST ? (tid & 31) : (tid & 63);

    // combine identity (tid < 448)
    const int cr = tid >> 6;
    const int cc = tid & 63;
    float cst = 0.f;

    float xreg = 0.f;
    if (act) xreg = in[((size_t)0 * BnP + b0 + sr) * DINP + si];

    for (int t = 0; t < Tn; t++) {
        if (act) in_s[sr][si] = xreg;
        __syncthreads();    // S1: x staged, h(t-1) visible, part(t-1) reads done

        // ---- phase A: partial gate pre-activations ----
        u64 acc0[NB], acc1[NB];
#pragma unroll
        for (int r = 0; r < NB; r++) { acc0[r] = binit0; acc1[r] = binit1; }
        const int qb = ks * (PP / 2);
#pragma unroll
        for (int q = 0; q < PP / 2; q++) {
#pragma unroll
            for (int r = 0; r < NB; r++) {
                ulonglong2 v = reinterpret_cast<const ulonglong2*>(&in_s[r][0])[qb + q];
                acc0[r] = fma2(w[0][2 * q],     v.x, acc0[r]);
                acc0[r] = fma2(w[0][2 * q + 1], v.y, acc0[r]);
                acc1[r] = fma2(w[1][2 * q],     v.x, acc1[r]);
                acc1[r] = fma2(w[1][2 * q + 1], v.y, acc1[r]);
            }
        }

        // prefetch next step's input (overlaps with tail of FMA phase)
        if (act && t + 1 < Tn)
            xreg = in[((size_t)(t + 1) * BnP + b0 + sr) * DINP + si];

#pragma unroll
        for (int r = 0; r < NB; r++) {
            float2 pv = make_float2(hadd2(acc0[r]), hadd2(acc1[r]));
            *reinterpret_cast<float2*>(&part[r][ks][g0]) = pv;
        }
        __syncthreads();    // S2: partials ready

        // ---- combine: reduce 4 K-quarters, activations, state update ----
        if (tid < NB * Hn) {
            float gi = 0.f, gf = 0.f, gg = 0.f, go = 0.f;
#pragma unroll
            for (int k2 = 0; k2 < 4; k2++) {
                gi += part[cr][k2][cc];
                gf += part[cr][k2][64  + cc];
                gg += part[cr][k2][128 + cc];
                go += part[cr][k2][192 + cc];
            }
            float iv = sigm(gi), fv = sigm(gf), gv = tanh_(gg), ov = sigm(go);
            cst = fv * cst + iv * gv;
            float h = ov * tanh_(cst);
            in_s[cr][DINP + cc] = h;
            if constexpr (!LAST) {
                if (cr < nrows)
                    outs[((size_t)t * BnP + b0 + cr) * Hn + cc] = h;
            }
        }
        // next S1 orders these writes before the next phase A
    }

    if constexpr (LAST) {
        __syncthreads();
        if (tid < nrows * 4) {
            const int r = tid >> 2, o = tid & 3;
            float s = b_fc[o];
#pragma unroll
            for (int k = 0; k < Hn; k++)
                s += in_s[r][DINP + k] * w_fc[o * Hn + k];
            out_fc[(b0 + r) * 4 + o] = s;
        }
    }
}

extern "C" void kernel_launch(void* const* d_in, const int* in_sizes, int n_in,
                              void* d_out, int out_size)
{
    const float* x    = (const float*)d_in[0];
    const float* wih0 = (const float*)d_in[1];
    const float* whh0 = (const float*)d_in[2];
    const float* bih0 = (const float*)d_in[3];
    const float* bhh0 = (const float*)d_in[4];
    const float* wih1 = (const float*)d_in[5];
    const float* whh1 = (const float*)d_in[6];
    const float* bih1 = (const float*)d_in[7];
    const float* bhh1 = (const float*)d_in[8];
    const float* wih2 = (const float*)d_in[9];
    const float* whh2 = (const float*)d_in[10];
    const float* bih2 = (const float*)d_in[11];
    const float* bhh2 = (const float*)d_in[12];
    const float* wfc  = (const float*)d_in[13];
    const float* bfc  = (const float*)d_in[14];
    float* out = (float*)d_out;

    transpose_x_k<<<Bn * 8, 256>>>(x);

    dim3 grid(GRID);      // 147 blocks, 1 per SM
    dim3 block(NT);       // 512 threads

    lstm_layer_k<0><<<grid, block>>>(wih0, whh0, bih0, bhh0, nullptr, nullptr, nullptr);
    lstm_layer_k<1><<<grid, block>>>(wih1, whh1, bih1, bhh1, nullptr, nullptr, nullptr);
    lstm_layer_k<2><<<grid, block>>>(wih2, whh2, bih2, bhh2, wfc,     bfc,     out);
}

// round 7
// speedup vs baseline: 2.5431x; 1.5405x over previous
#include <cuda_runtime.h>
#include <cuda_bf16.h>
#include <cstdint>
#include <cstddef>

namespace {
constexpr int Bn   = 1024;
constexpr int BnP  = 1032;   // padded rows (zero tail)
constexpr int Tn   = 512;
constexpr int Hn   = 64;
constexpr int NB   = 7;      // real batch rows per block -> grid 147 (N=8 with pad row)
constexpr int GRID = 147;
constexpr int NT   = 512;    // 16 warps
}

// Inter-layer activations, [t][b][64], f32, rows >=1024 stay zero.
__device__ float g_seq0[(size_t)Tn * BnP * 64];
__device__ float g_seq1[(size_t)Tn * BnP * 64];
// Layer-0 input transposed+padded: [t][b][64] (cols 22..63 zero)
__device__ float g_x64[(size_t)Tn * BnP * 64];

__device__ __forceinline__ float sigm(float x) {
    return __fdividef(1.f, 1.f + __expf(-x));
}
__device__ __forceinline__ float tanh_(float x) {
    return __fdividef(2.f, 1.f + __expf(-2.f * x)) - 1.f;
}
// pack two floats as bf16x2 (lo = first)
__device__ __forceinline__ uint32_t bf2(float a, float b) {
    __nv_bfloat162 t = __floats2bfloat162_rn(a, b);
    return *reinterpret_cast<uint32_t*>(&t);
}
__device__ __forceinline__ float bfr(float v) {   // round to bf16, back to f32
    return __bfloat162float(__float2bfloat16(v));
}

// m16n8k16 bf16 MMA, fp32 accumulate (sm_80 baseline PTX).
__device__ __forceinline__ void hmma(float& d0, float& d1, float& d2, float& d3,
                                     uint32_t a0, uint32_t a1, uint32_t a2, uint32_t a3,
                                     uint32_t b0, uint32_t b1) {
    asm volatile(
        "mma.sync.aligned.m16n8k16.row.col.f32.bf16.bf16.f32 "
        "{%0,%1,%2,%3}, {%4,%5,%6,%7}, {%8,%9}, {%0,%1,%2,%3};"
        : "+f"(d0), "+f"(d1), "+f"(d2), "+f"(d3)
        : "r"(a0), "r"(a1), "r"(a2), "r"(a3), "r"(b0), "r"(b1));
}

// Transpose x[b][22][t] -> g_x64[t][b][0..63] (cols 22..63 zero).
__global__ void __launch_bounds__(256)
transpose_x_k(const float* __restrict__ x)
{
    const int b  = blockIdx.x >> 3;
    const int t0 = (blockIdx.x & 7) * 64;
    __shared__ float tile[22][65];
    for (int e = threadIdx.x; e < 22 * 64; e += 256) {
        int i = e / 64, tt = e - i * 64;
        tile[i][tt] = x[(size_t)b * (22 * Tn) + i * Tn + t0 + tt];
    }
    __syncthreads();
    for (int e = threadIdx.x; e < 64 * 64; e += 256) {
        int tt = e >> 6, i = e & 63;
        g_x64[((size_t)(t0 + tt) * BnP + b) * 64 + i] = (i < 22) ? tile[i][tt] : 0.f;
    }
}

// One LSTM layer on HMMA tensor cores. Block owns 7 rows (+1 pad) for all T.
// Warp w owns gate m-tile [16w,16w+16); weights live in A-fragments (hi+lo bf16
// split). Per step: 8 k-chunks x 3 MMAs; gates exchanged through smem; combine
// thread (r,c) owns one cell, keeps c-state in a register, writes h (bf16
// hi/lo) back into the B tile for the next step.
template<int LAYER>
__global__ void __launch_bounds__(NT, 1)
lstm_hmma_k(const float* __restrict__ w_ih, const float* __restrict__ w_hh,
            const float* __restrict__ b_ih, const float* __restrict__ b_hh,
            const float* __restrict__ w_fc, const float* __restrict__ b_fc,
            float* __restrict__ out_fc)
{
    constexpr bool LAST = (LAYER == 2);
    constexpr int  DIN  = (LAYER == 0) ? 22 : 64;
    const float* xin  = (LAYER == 0) ? g_x64 : (LAYER == 1 ? g_seq0 : g_seq1);
    float*       outs = (LAYER == 0) ? g_seq0 : (LAYER == 1 ? g_seq1 : nullptr);

    // B tile (x_t | h), bf16 hi/lo, stride 136 bf16 -> conflict-free frag loads
    __shared__ __align__(16) __nv_bfloat16 in_hi[8][136];
    __shared__ __align__(16) __nv_bfloat16 in_lo[8][136];
    __shared__ float gates_s[8][268];      // [batch row][gate], padded stride
    __shared__ float h_s[8][64];

    const int tid  = threadIdx.x;
    const int lane = tid & 31;
    const int wrp  = tid >> 5;           // 0..15 -> m-tile
    const int gid  = lane >> 2;          // 0..7
    const int qid  = lane & 3;           // 0..3
    const int G    = wrp * 16;
    const int b0   = blockIdx.x * NB;
    const int nrows = (Bn - b0 < NB) ? (Bn - b0) : NB;

    // ---- load weights into A fragments (hi + lo bf16 split), registers ----
    const int m0 = G + gid;
    const int m1 = G + 8 + gid;
    uint32_t ahi[8][4], alo[8][4];
    {
        auto wld = [&](int m, int k) -> float {
            if (k < 64) return (k < DIN) ? w_ih[m * DIN + k] : 0.f;
            return w_hh[m * 64 + (k - 64)];
        };
#pragma unroll
        for (int kc = 0; kc < 8; kc++) {
            const int k0 = kc * 16 + qid * 2;
            const int k1 = k0 + 8;
            float v;
            float p00 = wld(m0, k0), p01 = wld(m0, k0 + 1);
            float p10 = wld(m1, k0), p11 = wld(m1, k0 + 1);
            float p20 = wld(m0, k1), p21 = wld(m0, k1 + 1);
            float p30 = wld(m1, k1), p31 = wld(m1, k1 + 1);
            ahi[kc][0] = bf2(bfr(p00), bfr(p01));
            ahi[kc][1] = bf2(bfr(p10), bfr(p11));
            ahi[kc][2] = bf2(bfr(p20), bfr(p21));
            ahi[kc][3] = bf2(bfr(p30), bfr(p31));
            alo[kc][0] = bf2(p00 - bfr(p00), p01 - bfr(p01));
            alo[kc][1] = bf2(p10 - bfr(p10), p11 - bfr(p11));
            alo[kc][2] = bf2(p20 - bfr(p20), p21 - bfr(p21));
            alo[kc][3] = bf2(p30 - bfr(p30), p31 - bfr(p31));
            (void)v;
        }
    }
    const float biasA = b_ih[m0] + b_hh[m0];
    const float biasB = b_ih[m1] + b_hh[m1];

    // ---- zero B tiles ----
    for (int e = tid; e < 8 * 136; e += NT) {
        (&in_hi[0][0])[e] = __float2bfloat16(0.f);
        (&in_lo[0][0])[e] = __float2bfloat16(0.f);
    }
    __syncthreads();

    // ---- combine identity: one cell per thread ----
    const int cr = tid >> 6;       // batch row 0..7 (7 = pad, computes garbage)
    const int cc = tid & 63;       // cell
    float cst = 0.f;

    // stage x(t=0) (pad rows read zeros from padded global arrays)
    {
        float v = xin[((size_t)0 * BnP + b0 + cr) * 64 + cc];
        float h = bfr(v);
        in_hi[cr][cc] = __float2bfloat16(h);
        in_lo[cr][cc] = __float2bfloat16(v - h);
    }

    // per-thread B-frag pointers (u32 view of in_* row gid, offset qid words)
    const uint32_t* rowH = reinterpret_cast<const uint32_t*>(&in_hi[gid][0]) + qid;
    const uint32_t* rowL = reinterpret_cast<const uint32_t*>(&in_lo[gid][0]) + qid;

    for (int t = 0; t < Tn; t++) {
        __syncthreads();   // B tile complete (x_t staged + h from prev combine)

        // prefetch next x (latency hidden behind the MMA phase)
        float xn = 0.f;
        if (t + 1 < Tn)
            xn = xin[((size_t)(t + 1) * BnP + b0 + cr) * 64 + cc];

        // ---- GEMM phase: 8 k-chunks x 3 split terms, 2 accumulator chains ----
        float d0 = biasA, d1 = biasA, d2 = biasB, d3 = biasB;
        float e0 = 0.f,   e1 = 0.f,   e2 = 0.f,   e3 = 0.f;
#pragma unroll
        for (int kc = 0; kc < 8; kc++) {
            const uint32_t bh0 = rowH[kc * 8];
            const uint32_t bh1 = rowH[kc * 8 + 4];
            const uint32_t bl0 = rowL[kc * 8];
            const uint32_t bl1 = rowL[kc * 8 + 4];
            hmma(d0, d1, d2, d3, ahi[kc][0], ahi[kc][1], ahi[kc][2], ahi[kc][3], bh0, bh1);
            hmma(e0, e1, e2, e3, ahi[kc][0], ahi[kc][1], ahi[kc][2], ahi[kc][3], bl0, bl1);
            hmma(d0, d1, d2, d3, alo[kc][0], alo[kc][1], alo[kc][2], alo[kc][3], bh0, bh1);
        }
        d0 += e0; d1 += e1; d2 += e2; d3 += e3;

        // ---- exchange gates: D(m,n) -> gates_s[n][m] (conflict-free) ----
        gates_s[qid * 2][m0]     = d0;
        gates_s[qid * 2 + 1][m0] = d1;
        gates_s[qid * 2][m1]     = d2;
        gates_s[qid * 2 + 1][m1] = d3;
        __syncthreads();   // gates ready; all B reads done -> B writable

        // ---- combine: activations + state update, one cell per thread ----
        const float gi = gates_s[cr][cc];
        const float gf = gates_s[cr][64 + cc];
        const float gg = gates_s[cr][128 + cc];
        const float go = gates_s[cr][192 + cc];
        const float iv = sigm(gi), fv = sigm(gf), gv = tanh_(gg), ov = sigm(go);
        cst = fv * cst + iv * gv;
        const float h = ov * tanh_(cst);

        // h back into B tile (k = 64 + cc), bf16 hi/lo
        {
            float hh = bfr(h);
            in_hi[cr][64 + cc] = __float2bfloat16(hh);
            in_lo[cr][64 + cc] = __float2bfloat16(h - hh);
        }
        if (cr < nrows) {
            if constexpr (!LAST)
                outs[((size_t)t * BnP + b0 + cr) * 64 + cc] = h;
            else if (t == Tn - 1)
                h_s[cr][cc] = h;
        }
        // next x into B tile (k = cc)
        if (t + 1 < Tn) {
            float hh = bfr(xn);
            in_hi[cr][cc] = __float2bfloat16(hh);
            in_lo[cr][cc] = __float2bfloat16(xn - hh);
        }
    }

    if constexpr (LAST) {
        __syncthreads();
        if (tid < nrows * 4) {
            const int r = tid >> 2, o = tid & 3;
            float s = b_fc[o];
#pragma unroll
            for (int k = 0; k < Hn; k++)
                s += h_s[r][k] * w_fc[o * Hn + k];
            out_fc[(b0 + r) * 4 + o] = s;
        }
    }
}

extern "C" void kernel_launch(void* const* d_in, const int* in_sizes, int n_in,
                              void* d_out, int out_size)
{
    const float* x    = (const float*)d_in[0];
    const float* wih0 = (const float*)d_in[1];
    const float* whh0 = (const float*)d_in[2];
    const float* bih0 = (const float*)d_in[3];
    const float* bhh0 = (const float*)d_in[4];
    const float* wih1 = (const float*)d_in[5];
    const float* whh1 = (const float*)d_in[6];
    const float* bih1 = (const float*)d_in[7];
    const float* bhh1 = (const float*)d_in[8];
    const float* wih2 = (const float*)d_in[9];
    const float* whh2 = (const float*)d_in[10];
    const float* bih2 = (const float*)d_in[11];
    const float* bhh2 = (const float*)d_in[12];
    const float* wfc  = (const float*)d_in[13];
    const float* bfc  = (const float*)d_in[14];
    float* out = (float*)d_out;

    transpose_x_k<<<Bn * 8, 256>>>(x);

    dim3 grid(GRID);
    dim3 block(NT);
    lstm_hmma_k<0><<<grid, block>>>(wih0, whh0, bih0, bhh0, nullptr, nullptr, nullptr);
    lstm_hmma_k<1><<<grid, block>>>(wih1, whh1, bih1, bhh1, nullptr, nullptr, nullptr);
    lstm_hmma_k<2><<<grid, block>>>(wih2, whh2, bih2, bhh2, wfc,     bfc,     out);
}

// round 8
// speedup vs baseline: 2.7153x; 1.0677x over previous
#include <cuda_runtime.h>
#include <cuda_bf16.h>
#include <cstdint>
#include <cstddef>

namespace {
constexpr int Bn   = 1024;
constexpr int BnP  = 1032;   // padded rows (zero tail)
constexpr int Tn   = 512;
constexpr int Hn   = 64;
constexpr int NB   = 7;      // real rows per block -> grid 147 (N=8 with pad row)
constexpr int GRID = 147;
constexpr int NT   = 512;    // 16 warps
}

// Inter-layer activations, [t][b][64], f32, rows >=1024 stay zero.
__device__ float g_seq0[(size_t)Tn * BnP * 64];
__device__ float g_seq1[(size_t)Tn * BnP * 64];
// Layer-0 input transposed+padded: [t][b][64] (cols 22..63 zero)
__device__ float g_x64[(size_t)Tn * BnP * 64];

__device__ __forceinline__ float sigm(float x) {
    return __fdividef(1.f, 1.f + __expf(-x));
}
__device__ __forceinline__ float tanh_(float x) {
    return __fdividef(2.f, 1.f + __expf(-2.f * x)) - 1.f;
}
__device__ __forceinline__ uint32_t bf2(float a, float b) {
    __nv_bfloat162 t = __floats2bfloat162_rn(a, b);
    return *reinterpret_cast<uint32_t*>(&t);
}
__device__ __forceinline__ float bfr(float v) {
    return __bfloat162float(__float2bfloat16(v));
}

// m16n8k16 bf16 MMA, fp32 accumulate (sm_80 baseline PTX).
__device__ __forceinline__ void hmma(float& d0, float& d1, float& d2, float& d3,
                                     uint32_t a0, uint32_t a1, uint32_t a2, uint32_t a3,
                                     uint32_t b0, uint32_t b1) {
    asm volatile(
        "mma.sync.aligned.m16n8k16.row.col.f32.bf16.bf16.f32 "
        "{%0,%1,%2,%3}, {%4,%5,%6,%7}, {%8,%9}, {%0,%1,%2,%3};"
        : "+f"(d0), "+f"(d1), "+f"(d2), "+f"(d3)
        : "r"(a0), "r"(a1), "r"(a2), "r"(a3), "r"(b0), "r"(b1));
}

// Transpose x[b][22][t] -> g_x64[t][b][0..63] (cols 22..63 zero).
__global__ void __launch_bounds__(256)
transpose_x_k(const float* __restrict__ x)
{
    const int b  = blockIdx.x >> 3;
    const int t0 = (blockIdx.x & 7) * 64;
    __shared__ float tile[22][65];
    for (int e = threadIdx.x; e < 22 * 64; e += 256) {
        int i = e / 64, tt = e - i * 64;
        tile[i][tt] = x[(size_t)b * (22 * Tn) + i * Tn + t0 + tt];
    }
    __syncthreads();
    for (int e = threadIdx.x; e < 64 * 64; e += 256) {
        int tt = e >> 6, i = e & 63;
        g_x64[((size_t)(t0 + tt) * BnP + b) * 64 + i] = (i < 22) ? tile[i][tt] : 0.f;
    }
}

// LSTM layer on HMMA tensor cores, x-projection hoisted off the critical path.
// B tile bf16 hi/lo, row stride 200 (words stride 100 -> conflict-free frags):
//   cols [0,64)   x slot 0      (parity double-buffer)
//   cols [64,128) x slot 1
//   cols [128,192) h_{t-1}
// Per step: hMMA (4 kc x 3 terms, init = carried xproj(t)) -> exchange ->
// xproj(t+1) (XCH kc x 3 terms, off critical path) -> barrier -> combine.
template<int LAYER>
__global__ void __launch_bounds__(NT, 1)
lstm_hmma_k(const float* __restrict__ w_ih, const float* __restrict__ w_hh,
            const float* __restrict__ b_ih, const float* __restrict__ b_hh,
            const float* __restrict__ w_fc, const float* __restrict__ b_fc,
            float* __restrict__ out_fc)
{
    constexpr bool LAST = (LAYER == 2);
    constexpr int  DIN  = (LAYER == 0) ? 22 : 64;
    constexpr int  XCH  = (LAYER == 0) ? 2 : 4;     // x k-chunks (cols >=32 zero for L0)
    const float* xin  = (LAYER == 0) ? g_x64 : (LAYER == 1 ? g_seq0 : g_seq1);
    float*       outs = (LAYER == 0) ? g_seq0 : (LAYER == 1 ? g_seq1 : nullptr);

    __shared__ __align__(16) __nv_bfloat16 in_hi[8][200];
    __shared__ __align__(16) __nv_bfloat16 in_lo[8][200];
    __shared__ float gates_s[8][268];
    __shared__ float h_s[8][64];

    const int tid  = threadIdx.x;
    const int lane = tid & 31;
    const int wrp  = tid >> 5;
    const int gid  = lane >> 2;
    const int qid  = lane & 3;
    const int G    = wrp * 16;
    const int b0   = blockIdx.x * NB;
    const int nrows = (Bn - b0 < NB) ? (Bn - b0) : NB;

    // ---- weight fragments (hi + lo bf16 split), registers ----
    const int m0 = G + gid;
    const int m1 = G + 8 + gid;
    uint32_t axh[XCH][4], axl[XCH][4];   // x cols [0,64)
    uint32_t ahh[4][4],   ahl[4][4];     // h cols [64,128)
    {
        auto pair = [&](float p0, float p1, uint32_t& hi, uint32_t& lo) {
            float h0 = bfr(p0), h1 = bfr(p1);
            hi = bf2(h0, h1);
            lo = bf2(p0 - h0, p1 - h1);
        };
        auto wx = [&](int m, int k) -> float {
            return (k < DIN) ? w_ih[m * DIN + k] : 0.f;
        };
#pragma unroll
        for (int kc = 0; kc < XCH; kc++) {
            const int k0 = kc * 16 + qid * 2, k1 = k0 + 8;
            pair(wx(m0, k0), wx(m0, k0 + 1), axh[kc][0], axl[kc][0]);
            pair(wx(m1, k0), wx(m1, k0 + 1), axh[kc][1], axl[kc][1]);
            pair(wx(m0, k1), wx(m0, k1 + 1), axh[kc][2], axl[kc][2]);
            pair(wx(m1, k1), wx(m1, k1 + 1), axh[kc][3], axl[kc][3]);
        }
#pragma unroll
        for (int kc = 0; kc < 4; kc++) {
            const int k0 = kc * 16 + qid * 2, k1 = k0 + 8;
            pair(w_hh[m0 * 64 + k0], w_hh[m0 * 64 + k0 + 1], ahh[kc][0], ahl[kc][0]);
            pair(w_hh[m1 * 64 + k0], w_hh[m1 * 64 + k0 + 1], ahh[kc][1], ahl[kc][1]);
            pair(w_hh[m0 * 64 + k1], w_hh[m0 * 64 + k1 + 1], ahh[kc][2], ahl[kc][2]);
            pair(w_hh[m1 * 64 + k1], w_hh[m1 * 64 + k1 + 1], ahh[kc][3], ahl[kc][3]);
        }
    }
    const float biasA = b_ih[m0] + b_hh[m0];
    const float biasB = b_ih[m1] + b_hh[m1];

    // ---- zero B tiles ----
    for (int e = tid; e < 8 * 200; e += NT) {
        (&in_hi[0][0])[e] = __float2bfloat16(0.f);
        (&in_lo[0][0])[e] = __float2bfloat16(0.f);
    }

    // combine identity
    const int cr = tid >> 6;       // batch row (7 = pad row)
    const int cc = tid & 63;
    float cst = 0.f;

    __syncthreads();
    // stage x_0 -> slot 0, x_1 -> slot 1
    {
        float v0 = xin[((size_t)0 * BnP + b0 + cr) * 64 + cc];
        float h0 = bfr(v0);
        in_hi[cr][cc] = __float2bfloat16(h0);
        in_lo[cr][cc] = __float2bfloat16(v0 - h0);
        float v1 = (Tn > 1) ? xin[((size_t)1 * BnP + b0 + cr) * 64 + cc] : 0.f;
        float h1 = bfr(v1);
        in_hi[cr][64 + cc] = __float2bfloat16(h1);
        in_lo[cr][64 + cc] = __float2bfloat16(v1 - h1);
    }
    __syncthreads();

    const uint32_t* rowH = reinterpret_cast<const uint32_t*>(&in_hi[gid][0]) + qid;
    const uint32_t* rowL = reinterpret_cast<const uint32_t*>(&in_lo[gid][0]) + qid;

    // xproj(t): reads x slot (t&1), returns carried accumulator (bias included)
    float cx0, cx1, cx2, cx3;
    auto xproj = [&](int slot) {
        float d0 = biasA, d1 = biasA, d2 = biasB, d3 = biasB;
        float e0 = 0.f, e1 = 0.f, e2 = 0.f, e3 = 0.f;
        float f0 = 0.f, f1 = 0.f, f2 = 0.f, f3 = 0.f;
        const int wb = 32 * slot;
#pragma unroll
        for (int kc = 0; kc < XCH; kc++) {
            const uint32_t bh0 = rowH[wb + kc * 8];
            const uint32_t bh1 = rowH[wb + kc * 8 + 4];
            const uint32_t bl0 = rowL[wb + kc * 8];
            const uint32_t bl1 = rowL[wb + kc * 8 + 4];
            hmma(d0, d1, d2, d3, axh[kc][0], axh[kc][1], axh[kc][2], axh[kc][3], bh0, bh1);
            hmma(e0, e1, e2, e3, axh[kc][0], axh[kc][1], axh[kc][2], axh[kc][3], bl0, bl1);
            hmma(f0, f1, f2, f3, axl[kc][0], axl[kc][1], axl[kc][2], axl[kc][3], bh0, bh1);
        }
        cx0 = d0 + e0 + f0; cx1 = d1 + e1 + f1;
        cx2 = d2 + e2 + f2; cx3 = d3 + e3 + f3;
    };

    xproj(0);   // carried for t=0

    for (int t = 0; t < Tn; t++) {
        __syncthreads();   // h_{t-1} + x slots staged

        // ---- critical-path GEMM: W_h · h_{t-1}, init = carried xproj(t) ----
        float d0 = cx0, d1 = cx1, d2 = cx2, d3 = cx3;
        float e0 = 0.f, e1 = 0.f, e2 = 0.f, e3 = 0.f;
        float f0 = 0.f, f1 = 0.f, f2 = 0.f, f3 = 0.f;
#pragma unroll
        for (int kc = 0; kc < 4; kc++) {
            const uint32_t bh0 = rowH[64 + kc * 8];
            const uint32_t bh1 = rowH[64 + kc * 8 + 4];
            const uint32_t bl0 = rowL[64 + kc * 8];
            const uint32_t bl1 = rowL[64 + kc * 8 + 4];
            hmma(d0, d1, d2, d3, ahh[kc][0], ahh[kc][1], ahh[kc][2], ahh[kc][3], bh0, bh1);
            hmma(e0, e1, e2, e3, ahh[kc][0], ahh[kc][1], ahh[kc][2], ahh[kc][3], bl0, bl1);
            hmma(f0, f1, f2, f3, ahl[kc][0], ahl[kc][1], ahl[kc][2], ahl[kc][3], bh0, bh1);
        }
        d0 += e0 + f0; d1 += e1 + f1; d2 += e2 + f2; d3 += e3 + f3;

        // ---- exchange gates: D(m,n) -> gates_s[n][m] ----
        gates_s[qid * 2][m0]     = d0;
        gates_s[qid * 2 + 1][m0] = d1;
        gates_s[qid * 2][m1]     = d2;
        gates_s[qid * 2 + 1][m1] = d3;

        // ---- off-path: xproj(t+1) from slot (t+1)&1 ----
        if (t + 1 < Tn) xproj((t + 1) & 1);

        // prefetch x_{t+2}
        float xn = 0.f;
        if (t + 2 < Tn)
            xn = xin[((size_t)(t + 2) * BnP + b0 + cr) * 64 + cc];

        __syncthreads();   // gates ready; B-tile reads done

        // ---- combine: one cell per thread ----
        const float gi = gates_s[cr][cc];
        const float gf = gates_s[cr][64 + cc];
        const float gg = gates_s[cr][128 + cc];
        const float go = gates_s[cr][192 + cc];
        const float iv = sigm(gi), fv = sigm(gf), gv = tanh_(gg), ov = sigm(go);
        cst = fv * cst + iv * gv;
        const float h = ov * tanh_(cst);

        // h into B-tile h slot
        {
            float hh = bfr(h);
            in_hi[cr][128 + cc] = __float2bfloat16(hh);
            in_lo[cr][128 + cc] = __float2bfloat16(h - hh);
        }
        // x_{t+2} into slot t&1 (slot (t+1)&1 was just consumed by xproj)
        if (t + 2 < Tn) {
            float hh = bfr(xn);
            const int xb = 64 * (t & 1);
            in_hi[cr][xb + cc] = __float2bfloat16(hh);
            in_lo[cr][xb + cc] = __float2bfloat16(xn - hh);
        }
        if (cr < nrows) {
            if constexpr (!LAST)
                outs[((size_t)t * BnP + b0 + cr) * 64 + cc] = h;
            else if (t == Tn - 1)
                h_s[cr][cc] = h;
        }
    }

    if constexpr (LAST) {
        __syncthreads();
        if (tid < nrows * 4) {
            const int r = tid >> 2, o = tid & 3;
            float s = b_fc[o];
#pragma unroll
            for (int k = 0; k < Hn; k++)
                s += h_s[r][k] * w_fc[o * Hn + k];
            out_fc[(b0 + r) * 4 + o] = s;
        }
    }
}

extern "C" void kernel_launch(void* const* d_in, const int* in_sizes, int n_in,
                              void* d_out, int out_size)
{
    const float* x    = (const float*)d_in[0];
    const float* wih0 = (const float*)d_in[1];
    const float* whh0 = (const float*)d_in[2];
    const float* bih0 = (const float*)d_in[3];
    const float* bhh0 = (const float*)d_in[4];
    const float* wih1 = (const float*)d_in[5];
    const float* whh1 = (const float*)d_in[6];
    const float* bih1 = (const float*)d_in[7];
    const float* bhh1 = (const float*)d_in[8];
    const float* wih2 = (const float*)d_in[9];
    const float* whh2 = (const float*)d_in[10];
    const float* bih2 = (const float*)d_in[11];
    const float* bhh2 = (const float*)d_in[12];
    const float* wfc  = (const float*)d_in[13];
    const float* bfc  = (const float*)d_in[14];
    float* out = (float*)d_out;

    transpose_x_k<<<Bn * 8, 256>>>(x);

    dim3 grid(GRID);
    dim3 block(NT);
    lstm_hmma_k<0><<<grid, block>>>(wih0, whh0, bih0, bhh0, nullptr, nullptr, nullptr);
    lstm_hmma_k<1><<<grid, block>>>(wih1, whh1, bih1, bhh1, nullptr, nullptr, nullptr);
    lstm_hmma_k<2><<<grid, block>>>(wih2, whh2, bih2, bhh2, wfc,     bfc,     out);
}